// round 13
// baseline (speedup 1.0000x reference)
#include <cuda_runtime.h>
#include <cuda_bf16.h>
#include <cstdint>

#define MAX_W 16384
__device__ float g_half_sum[MAX_W];
__device__ int   g_done_ctr = 0;

__device__ __forceinline__ uint32_t smem_u32(const void* p) {
    uint32_t a;
    asm("{ .reg .u64 t; cvta.to.shared.u64 t, %1; cvt.u32.u64 %0, t; }"
        : "=r"(a) : "l"(p));
    return a;
}
__device__ __forceinline__ void cp_async16(uint32_t dst, const void* src) {
    asm volatile("cp.async.cg.shared.global [%0], [%1], 16;"
                 :: "r"(dst), "l"(src) : "memory");
}
__device__ __forceinline__ void cp_commit() {
    asm volatile("cp.async.commit_group;" ::: "memory");
}
__device__ __forceinline__ void cp_wait_dyn(int n) {
    switch (n) {
    case 0:  asm volatile("cp.async.wait_group 0;" ::: "memory"); break;
    case 1:  asm volatile("cp.async.wait_group 1;" ::: "memory"); break;
    case 2:  asm volatile("cp.async.wait_group 2;" ::: "memory"); break;
    default: asm volatile("cp.async.wait_group 3;" ::: "memory"); break;
    }
}

// ---------------------------------------------------------------------------
// Two warps per row, contiguous halves of the VALID prefix, cp.async ring.
//   warp w -> row w>>1, half w&1; half 0 = chunks [0,Vh), half 1 = [Vh,V)
//   with Vh=(V+1)/2 -> equal work per pair, contiguous streaming.
//   8192 warps -> ~55 warps/SM (occ ~86%) in one wave; per-thread cp.async
//   keeps bytes-in-flight off the register file; each lane reads back only
//   its own smem slot -> no barriers.
//   loss = (1/B) * sum_row (1/L) * sum_{t<L} (pred - log(align))^2
// Deterministic: static ownership, fixed accumulation & reduce order.
// ---------------------------------------------------------------------------
template <int BLOCK>
__global__ void __launch_bounds__(BLOCK)
dploss_half_kernel(const float* __restrict__ pred,
                   const float* __restrict__ align,
                   const int* __restrict__ lens,
                   float* __restrict__ out,
                   int C, int B, int nW) {
    // Per warp: 4 stages x 1KB (stage = 32 x 16B pred + 32 x 16B align).
    __shared__ __align__(16) char ring[(BLOCK / 32) * 4096];
    const int lane = threadIdx.x & 31;
    const int wic  = threadIdx.x >> 5;
    const int w    = (blockIdx.x * BLOCK + threadIdx.x) >> 5;

    const uint32_t sbase = smem_u32(ring) + (uint32_t)wic * 4096u;

    if (w < nW) {
        const int row  = w >> 1;
        const int half = w & 1;
        const int L = __ldg(lens + row);
        const int V = (L + 3) >> 2;             // valid chunks (incl. partial)
        const int Vh = (V + 1) >> 1;
        const int s0 = half ? Vh : 0;
        const int s1 = half ? V  : Vh;
        const int span = s1 - s0;
        const int tiles = (span + 31) >> 5;

        const size_t gbase = (size_t)row * (size_t)C;
        const float4* __restrict__ p4 = reinterpret_cast<const float4*>(pred) + gbase;
        const float4* __restrict__ a4 = reinterpret_cast<const float4*>(align) + gbase;

        // Prologue: up to 3 tiles ahead.
        const int pre = min(tiles, 3);
        for (int t = 0; t < pre; t++) {
            const int c = s0 + (t << 5) + lane;
            const uint32_t dst = sbase + (uint32_t)((t & 3) << 10) + (uint32_t)(lane << 4);
            if (c < s1) {
                cp_async16(dst,        p4 + c);
                cp_async16(dst + 512u, a4 + c);
            }
            cp_commit();
        }

        float s = 0.0f;
        for (int t = 0; t < tiles; t++) {
            if (t + 3 < tiles) {
                const int ci = s0 + ((t + 3) << 5) + lane;
                const uint32_t dst = sbase + (uint32_t)(((t + 3) & 3) << 10)
                                   + (uint32_t)(lane << 4);
                if (ci < s1) {
                    cp_async16(dst,        p4 + ci);
                    cp_async16(dst + 512u, a4 + ci);
                }
                cp_commit();
                cp_wait_dyn(3);
            } else {
                cp_wait_dyn(tiles - 1 - t);
            }

            const int c = s0 + (t << 5) + lane;
            if (c < s1) {
                const char* sp = ring + (size_t)wic * 4096
                               + (size_t)((t & 3) << 10) + (size_t)(lane << 4);
                float4 p = *reinterpret_cast<const float4*>(sp);
                float4 a = *reinterpret_cast<const float4*>(sp + 512);
                const int rem = L - (c << 2);
                float d = p.x - __logf(a.x);
                s = fmaf(d, d, s);
                if (rem > 1) { d = p.y - __logf(a.y); s = fmaf(d, d, s); }
                if (rem > 2) { d = p.z - __logf(a.z); s = fmaf(d, d, s); }
                if (rem > 3) { d = p.w - __logf(a.w); s = fmaf(d, d, s); }
            }
        }

        // Warp reduction (fixed order -> deterministic).
        #pragma unroll
        for (int off = 16; off > 0; off >>= 1)
            s += __shfl_down_sync(0xFFFFFFFFu, s, off);
        if (lane == 0)
            g_half_sum[w] = s * __frcp_rn((float)L);
    }

    // Completion signal; last CTA reduces all half-sums in fixed order.
    __syncthreads();
    __shared__ bool s_is_last;
    if (threadIdx.x == 0) {
        __threadfence();
        int old = atomicAdd(&g_done_ctr, 1);
        s_is_last = (old == (int)gridDim.x - 1);
    }
    __syncthreads();

    if (s_is_last) {
        float v = 0.0f;
        for (int i = threadIdx.x; i < nW; i += BLOCK)   // fixed strided order
            v += g_half_sum[i];
        __shared__ float s_fin[BLOCK / 32];
        #pragma unroll
        for (int off = 16; off > 0; off >>= 1)
            v += __shfl_down_sync(0xFFFFFFFFu, v, off);
        if ((threadIdx.x & 31) == 0) s_fin[threadIdx.x >> 5] = v;
        __syncthreads();
        if (threadIdx.x == 0) {
            float t = 0.0f;
            #pragma unroll
            for (int k = 0; k < BLOCK / 32; k++) t += s_fin[k];
            out[0] = t / (float)B;
            g_done_ctr = 0;                    // reset for next graph replay
        }
    }
}

extern "C" void kernel_launch(void* const* d_in, const int* in_sizes, int n_in,
                              void* d_out, int out_size) {
    const float* pred  = (const float*)d_in[0];
    const float* align = (const float*)d_in[1];
    const int*   lens  = (const int*)d_in[2];
    float* out = (float*)d_out;

    const int B = in_sizes[2];
    const int T = in_sizes[0] / B;
    const int C = T >> 2;
    int nW = B * 2;                               // 2 half-warps per row
    if (nW > MAX_W) nW = MAX_W;

    constexpr int BLOCK = 128;                    // 4 warps/CTA, 16KB smem
    int grid = (nW + (BLOCK / 32) - 1) / (BLOCK / 32);
    if (grid < 1) grid = 1;

    // Max shared-memory carveout so 14 CTAs/SM fit (one resident wave).
    static bool configured = false;
    if (!configured) {
        cudaFuncSetAttribute(dploss_half_kernel<BLOCK>,
                             cudaFuncAttributePreferredSharedMemoryCarveout,
                             (int)cudaSharedmemCarveoutMaxShared);
        configured = true;
    }

    dploss_half_kernel<BLOCK><<<grid, BLOCK>>>(pred, align, lens, out, C, B, nW);
}